// round 3
// baseline (speedup 1.0000x reference)
#include <cuda_runtime.h>
#include <cuda_bf16.h>

// Problem constants (fixed by reference setup_inputs)
#define BB 1024
#define NN 4096
#define CC 21
#define NTHREADS 256

// Scratch (__device__ globals are the allowed scratch path)
__device__ float g_partials[BB];
__device__ unsigned int g_count;   // zero-initialized; last block resets it each call

__device__ __forceinline__ float point_norm(float x, float y, float z,
                                            float c0, float c1, float c2,
                                            float c3, float c4, float c5) {
    // q = c0*x^2 + c1*y^2 + c2*z^2 + c3*x*y + c4*x*z + c5*y*z  (c3..c5 carry the 2x)
    float q = fmaf(x, fmaf(c0, x, fmaf(c3, y, c4 * z)),
               fmaf(y, fmaf(c1, y, c5 * z),
                    c2 * z * z));
    // sqrt(q) via q * rsqrt(q); guard q<=0 (rounding can give tiny negatives)
    return (q > 0.0f) ? q * __frsqrt_rn(q) : 0.0f;
}

__global__ void __launch_bounds__(NTHREADS)
point_loss_fused_kernel(const float* __restrict__ pred_q,
                        const float* __restrict__ gt_q,
                        const void* __restrict__ cls_raw,
                        const float* __restrict__ bank,
                        float* __restrict__ out) {
    const int b = blockIdx.x;
    const int tid = threadIdx.x;

    __shared__ float sc[6];
    __shared__ int   s_is64;
    __shared__ float swarp[NTHREADS / 32];
    __shared__ bool  s_last;

    // ---- warp 0: dtype detection + Gram coefficients ----
    if (tid < 32) {
        // int64 layout (LE): odd int32 words are high halves == 0 (values < 21).
        // int32 layout: odd words are class values; P(64 of them all zero) ~ 21^-64.
        const int* cls32 = (const int*)cls_raw;
        int all_zero = 1;
        #pragma unroll
        for (int i = tid; i < 64; i += 32)
            if (cls32[2 * i + 1] != 0) all_zero = 0;
        all_zero = __all_sync(0xffffffffu, all_zero);
        if (tid == 0) s_is64 = all_zero;
    }
    if (tid == 0) {
        // Build R_pred, R_gt exactly per reference quaternion_to_matrix
        float Rp[9], Rg[9];
        {
            float x = pred_q[4 * b + 0], y = pred_q[4 * b + 1];
            float z = pred_q[4 * b + 2], w = pred_q[4 * b + 3];
            float x2 = x * x, y2 = y * y, z2 = z * z;
            float xy = x * y, xz = x * z, yz = y * z;
            float wx = w * x, wy = w * y, wz = w * z;
            Rp[0] = 1.0f - 2.0f * (y2 + z2); Rp[1] = 2.0f * (xy - wz); Rp[2] = 2.0f * (xz + wy);
            Rp[3] = 2.0f * (xy + wz); Rp[4] = 1.0f - 2.0f * (x2 + z2); Rp[5] = 2.0f * (yz - wx);
            Rp[6] = 2.0f * (xz - wy); Rp[7] = 2.0f * (yz + wx); Rp[8] = 1.0f - 2.0f * (x2 + y2);
        }
        {
            float x = gt_q[4 * b + 0], y = gt_q[4 * b + 1];
            float z = gt_q[4 * b + 2], w = gt_q[4 * b + 3];
            float x2 = x * x, y2 = y * y, z2 = z * z;
            float xy = x * y, xz = x * z, yz = y * z;
            float wx = w * x, wy = w * y, wz = w * z;
            Rg[0] = 1.0f - 2.0f * (y2 + z2); Rg[1] = 2.0f * (xy - wz); Rg[2] = 2.0f * (xz + wy);
            Rg[3] = 2.0f * (xy + wz); Rg[4] = 1.0f - 2.0f * (x2 + z2); Rg[5] = 2.0f * (yz - wx);
            Rg[6] = 2.0f * (xz - wy); Rg[7] = 2.0f * (yz + wx); Rg[8] = 1.0f - 2.0f * (x2 + y2);
        }
        float d[9];
        #pragma unroll
        for (int i = 0; i < 9; i++) d[i] = Rp[i] - Rg[i];

        // M = dR^T dR (symmetric). Column k of dR is d[k], d[k+3], d[k+6].
        sc[0] = d[0]*d[0] + d[3]*d[3] + d[6]*d[6];
        sc[1] = d[1]*d[1] + d[4]*d[4] + d[7]*d[7];
        sc[2] = d[2]*d[2] + d[5]*d[5] + d[8]*d[8];
        sc[3] = 2.0f * (d[0]*d[1] + d[3]*d[4] + d[6]*d[7]);
        sc[4] = 2.0f * (d[0]*d[2] + d[3]*d[5] + d[6]*d[8]);
        sc[5] = 2.0f * (d[1]*d[2] + d[4]*d[5] + d[7]*d[8]);
    }
    __syncthreads();

    const float c0 = sc[0], c1 = sc[1], c2 = sc[2];
    const float c3 = sc[3], c4 = sc[4], c5 = sc[5];

    // Class index (dtype-robust + clamped: wrong guess -> rel_err, never a crash)
    int cidx;
    if (s_is64) cidx = (int)((const long long*)cls_raw)[b];
    else        cidx = ((const int*)cls_raw)[b];
    cidx = min(max(cidx, 0), CC - 1);

    const float4* __restrict__ base4 =
        (const float4*)(bank + (size_t)cidx * (size_t)(NN * 3));

    float acc = 0.0f;
    // 4096 points = 1024 "triples" of 3 float4 (= 4 points each)
    #pragma unroll
    for (int it = 0; it < (NN / 4) / NTHREADS; ++it) {
        int tri = it * NTHREADS + tid;
        float4 a = base4[tri * 3 + 0];
        float4 v = base4[tri * 3 + 1];
        float4 w = base4[tri * 3 + 2];
        acc += point_norm(a.x, a.y, a.z, c0, c1, c2, c3, c4, c5);
        acc += point_norm(a.w, v.x, v.y, c0, c1, c2, c3, c4, c5);
        acc += point_norm(v.z, v.w, w.x, c0, c1, c2, c3, c4, c5);
        acc += point_norm(w.y, w.z, w.w, c0, c1, c2, c3, c4, c5);
    }

    // ---- block reduce ----
    #pragma unroll
    for (int o = 16; o > 0; o >>= 1)
        acc += __shfl_xor_sync(0xffffffffu, acc, o);
    if ((tid & 31) == 0) swarp[tid >> 5] = acc;
    __syncthreads();
    if (tid == 0) {
        float s = 0.0f;
        #pragma unroll
        for (int i = 0; i < NTHREADS / 32; i++) s += swarp[i];
        g_partials[b] = s;
        __threadfence();
        unsigned int ticket = atomicAdd(&g_count, 1u);
        s_last = (ticket == BB - 1);
    }
    __syncthreads();

    // ---- last block: deterministic fixed-order final reduce ----
    if (s_last) {
        __threadfence();  // acquire: make all g_partials visible
        __shared__ double sm[NTHREADS];
        double s = (double)g_partials[tid]
                 + (double)g_partials[tid + 256]
                 + (double)g_partials[tid + 512]
                 + (double)g_partials[tid + 768];
        sm[tid] = s;
        __syncthreads();
        #pragma unroll
        for (int o = NTHREADS / 2; o > 0; o >>= 1) {
            if (tid < o) sm[tid] += sm[tid + o];
            __syncthreads();
        }
        if (tid == 0) {
            out[0] = (float)(sm[0] / (double)((long long)BB * NN));
            g_count = 0;  // reset for next graph replay
        }
    }
}

extern "C" void kernel_launch(void* const* d_in, const int* in_sizes, int n_in,
                              void* d_out, int out_size) {
    // Resolve inputs by element count (robust to metadata ordering):
    //   pred_q / gt_q : 4096 elems (order of appearance; loss is symmetric in swap)
    //   class_indices : 1024 elems
    //   point_bank    : 258048 elems
    const float* pred_q = nullptr;
    const float* gt_q   = nullptr;
    const void*  cls    = nullptr;
    const float* bank   = nullptr;

    for (int i = 0; i < n_in; i++) {
        int sz = in_sizes[i];
        if (sz == BB) {
            cls = d_in[i];
        } else if (sz == CC * NN * 3) {
            bank = (const float*)d_in[i];
        } else if (sz == BB * 4) {
            if (!pred_q) pred_q = (const float*)d_in[i];
            else         gt_q   = (const float*)d_in[i];
        }
    }
    float* out = (float*)d_out;

    point_loss_fused_kernel<<<BB, NTHREADS>>>(pred_q, gt_q, cls, bank, out);
}

// round 4
// speedup vs baseline: 1.4915x; 1.4915x over previous
#include <cuda_runtime.h>
#include <cuda_bf16.h>

// Problem constants (fixed by reference setup_inputs)
#define BB 1024
#define NN 4096
#define CC 21
#define NTHREADS 256

// Scratch (__device__ globals are the allowed scratch path)
__device__ float g_partials[BB];

__device__ __forceinline__ float point_norm(float x, float y, float z,
                                            float c0, float c1, float c2,
                                            float c3, float c4, float c5) {
    // q = c0*x^2 + c1*y^2 + c2*z^2 + c3*x*y + c4*x*z + c5*y*z  (c3..c5 carry the 2x)
    float q = fmaf(x, fmaf(c0, x, fmaf(c3, y, c4 * z)),
               fmaf(y, fmaf(c1, y, c5 * z),
                    c2 * z * z));
    // sqrt(q) = q * rsqrt(q); clamp avoids 0*inf=nan at q<=0 (maps to ~0)
    return q * __frsqrt_rn(fmaxf(q, 1e-38f));
}

__global__ void __launch_bounds__(NTHREADS)
point_loss_kernel(const float* __restrict__ pred_q,
                  const float* __restrict__ gt_q,
                  const void* __restrict__ cls_raw,
                  const float* __restrict__ bank) {
    const int b = blockIdx.x;
    const int tid = threadIdx.x;

    __shared__ float sc[6];
    __shared__ int   s_is64;
    __shared__ float swarp[NTHREADS / 32];

    // ---- warp 0: dtype detection; thread 0: Gram coefficients ----
    if (tid < 32) {
        // int64 layout (LE): odd int32 words are high halves == 0 (values < 21).
        // int32 layout: odd words are class values; P(all 64 zero) ~ 21^-64.
        const int* cls32 = (const int*)cls_raw;
        int all_zero = 1;
        #pragma unroll
        for (int i = tid; i < 64; i += 32)
            if (cls32[2 * i + 1] != 0) all_zero = 0;
        all_zero = __all_sync(0xffffffffu, all_zero);
        if (tid == 0) s_is64 = all_zero;
    }
    if (tid == 0) {
        // Build R_pred, R_gt exactly per reference quaternion_to_matrix
        float Rp[9], Rg[9];
        {
            float x = pred_q[4 * b + 0], y = pred_q[4 * b + 1];
            float z = pred_q[4 * b + 2], w = pred_q[4 * b + 3];
            float x2 = x * x, y2 = y * y, z2 = z * z;
            float xy = x * y, xz = x * z, yz = y * z;
            float wx = w * x, wy = w * y, wz = w * z;
            Rp[0] = 1.0f - 2.0f * (y2 + z2); Rp[1] = 2.0f * (xy - wz); Rp[2] = 2.0f * (xz + wy);
            Rp[3] = 2.0f * (xy + wz); Rp[4] = 1.0f - 2.0f * (x2 + z2); Rp[5] = 2.0f * (yz - wx);
            Rp[6] = 2.0f * (xz - wy); Rp[7] = 2.0f * (yz + wx); Rp[8] = 1.0f - 2.0f * (x2 + y2);
        }
        {
            float x = gt_q[4 * b + 0], y = gt_q[4 * b + 1];
            float z = gt_q[4 * b + 2], w = gt_q[4 * b + 3];
            float x2 = x * x, y2 = y * y, z2 = z * z;
            float xy = x * y, xz = x * z, yz = y * z;
            float wx = w * x, wy = w * y, wz = w * z;
            Rg[0] = 1.0f - 2.0f * (y2 + z2); Rg[1] = 2.0f * (xy - wz); Rg[2] = 2.0f * (xz + wy);
            Rg[3] = 2.0f * (xy + wz); Rg[4] = 1.0f - 2.0f * (x2 + z2); Rg[5] = 2.0f * (yz - wx);
            Rg[6] = 2.0f * (xz - wy); Rg[7] = 2.0f * (yz + wx); Rg[8] = 1.0f - 2.0f * (x2 + y2);
        }
        float d[9];
        #pragma unroll
        for (int i = 0; i < 9; i++) d[i] = Rp[i] - Rg[i];

        // M = dR^T dR (symmetric). Column k of dR is d[k], d[k+3], d[k+6].
        sc[0] = d[0]*d[0] + d[3]*d[3] + d[6]*d[6];
        sc[1] = d[1]*d[1] + d[4]*d[4] + d[7]*d[7];
        sc[2] = d[2]*d[2] + d[5]*d[5] + d[8]*d[8];
        sc[3] = 2.0f * (d[0]*d[1] + d[3]*d[4] + d[6]*d[7]);
        sc[4] = 2.0f * (d[0]*d[2] + d[3]*d[5] + d[6]*d[8]);
        sc[5] = 2.0f * (d[1]*d[2] + d[4]*d[5] + d[7]*d[8]);
    }
    __syncthreads();

    const float c0 = sc[0], c1 = sc[1], c2 = sc[2];
    const float c3 = sc[3], c4 = sc[4], c5 = sc[5];

    // Class index (dtype-robust + clamped: wrong guess -> rel_err, never a crash)
    int cidx;
    if (s_is64) cidx = (int)((const long long*)cls_raw)[b];
    else        cidx = ((const int*)cls_raw)[b];
    cidx = min(max(cidx, 0), CC - 1);

    const float4* __restrict__ base4 =
        (const float4*)(bank + (size_t)cidx * (size_t)(NN * 3));

    // Software-pipelined, fully unrolled: 4 iterations x 3 float4 (= 4 points each).
    // Independent accumulators break the serial FADD chain.
    float acc0 = 0.0f, acc1 = 0.0f, acc2 = 0.0f, acc3 = 0.0f;

    float4 a = base4[tid * 3 + 0];
    float4 v = base4[tid * 3 + 1];
    float4 w = base4[tid * 3 + 2];

    #pragma unroll
    for (int it = 0; it < (NN / 4) / NTHREADS; ++it) {
        float4 na, nv, nw;
        if (it < (NN / 4) / NTHREADS - 1) {
            int tri = (it + 1) * NTHREADS + tid;
            na = base4[tri * 3 + 0];
            nv = base4[tri * 3 + 1];
            nw = base4[tri * 3 + 2];
        }
        acc0 += point_norm(a.x, a.y, a.z, c0, c1, c2, c3, c4, c5);
        acc1 += point_norm(a.w, v.x, v.y, c0, c1, c2, c3, c4, c5);
        acc2 += point_norm(v.z, v.w, w.x, c0, c1, c2, c3, c4, c5);
        acc3 += point_norm(w.y, w.z, w.w, c0, c1, c2, c3, c4, c5);
        a = na; v = nv; w = nw;
    }

    float acc = (acc0 + acc1) + (acc2 + acc3);

    // ---- block reduce ----
    #pragma unroll
    for (int o = 16; o > 0; o >>= 1)
        acc += __shfl_xor_sync(0xffffffffu, acc, o);
    if ((tid & 31) == 0) swarp[tid >> 5] = acc;
    __syncthreads();
    if (tid == 0) {
        float s = 0.0f;
        #pragma unroll
        for (int i = 0; i < NTHREADS / 32; i++) s += swarp[i];
        g_partials[b] = s;
    }
}

__global__ void __launch_bounds__(256)
reduce_kernel(float* __restrict__ out) {
    __shared__ double sm[256];
    int t = threadIdx.x;
    double s = (double)g_partials[t]
             + (double)g_partials[t + 256]
             + (double)g_partials[t + 512]
             + (double)g_partials[t + 768];
    sm[t] = s;
    __syncthreads();
    #pragma unroll
    for (int o = 128; o > 0; o >>= 1) {
        if (t < o) sm[t] += sm[t + o];
        __syncthreads();
    }
    if (t == 0) out[0] = (float)(sm[0] / (double)((long long)BB * NN));
}

extern "C" void kernel_launch(void* const* d_in, const int* in_sizes, int n_in,
                              void* d_out, int out_size) {
    // Resolve inputs by element count (robust to metadata ordering):
    //   pred_q / gt_q : 4096 elems (order of appearance; loss is symmetric in swap)
    //   class_indices : 1024 elems
    //   point_bank    : 258048 elems
    const float* pred_q = nullptr;
    const float* gt_q   = nullptr;
    const void*  cls    = nullptr;
    const float* bank   = nullptr;

    for (int i = 0; i < n_in; i++) {
        int sz = in_sizes[i];
        if (sz == BB) {
            cls = d_in[i];
        } else if (sz == CC * NN * 3) {
            bank = (const float*)d_in[i];
        } else if (sz == BB * 4) {
            if (!pred_q) pred_q = (const float*)d_in[i];
            else         gt_q   = (const float*)d_in[i];
        }
    }
    float* out = (float*)d_out;

    point_loss_kernel<<<BB, NTHREADS>>>(pred_q, gt_q, cls, bank);
    reduce_kernel<<<1, 256>>>(out);
}

// round 5
// speedup vs baseline: 1.5644x; 1.0489x over previous
#include <cuda_runtime.h>
#include <cuda_bf16.h>

// Problem constants (fixed by reference setup_inputs)
#define BB 1024
#define NN 4096
#define CC 21
#define NTHREADS 256

// Scratch (__device__ globals are the allowed scratch path)
__device__ float g_partials[BB];

__device__ __forceinline__ float sqrt_approx(float x) {
    float r;
    asm("sqrt.approx.f32 %0, %1;" : "=f"(r) : "f"(x));
    return r;  // single MUFU.SQRT, rel err ~2^-20
}

__device__ __forceinline__ float point_norm(float x, float y, float z,
                                            float c0, float c1, float c2,
                                            float c3, float c4, float c5) {
    // q = c0*x^2 + c1*y^2 + c2*z^2 + c3*x*y + c4*x*z + c5*y*z  (c3..c5 carry the 2x)
    float q = fmaf(x, fmaf(c0, x, fmaf(c3, y, c4 * z)),
               fmaf(y, fmaf(c1, y, c5 * z),
                    c2 * z * z));
    // M is PSD; clamp tiny negative rounding results to 0 (sqrt.approx(0)=0)
    return sqrt_approx(fmaxf(q, 0.0f));
}

__global__ void __launch_bounds__(NTHREADS)
point_loss_kernel(const float* __restrict__ pred_q,
                  const float* __restrict__ gt_q,
                  const void* __restrict__ cls_raw,
                  const float* __restrict__ bank) {
    const int b = blockIdx.x;
    const int tid = threadIdx.x;

    __shared__ float sc[6];
    __shared__ int   s_is64;
    __shared__ float swarp[NTHREADS / 32];

    // ---- warp 0: dtype detection; thread 0: Gram coefficients ----
    if (tid < 32) {
        // int64 layout (LE): odd int32 words are high halves == 0 (values < 21).
        // int32 layout: odd words are class values; P(all 64 zero) ~ 21^-64.
        const int* cls32 = (const int*)cls_raw;
        int all_zero = 1;
        #pragma unroll
        for (int i = tid; i < 64; i += 32)
            if (cls32[2 * i + 1] != 0) all_zero = 0;
        all_zero = __all_sync(0xffffffffu, all_zero);
        if (tid == 0) s_is64 = all_zero;
    }
    if (tid == 0) {
        // Build R_pred, R_gt exactly per reference quaternion_to_matrix
        float Rp[9], Rg[9];
        {
            float x = pred_q[4 * b + 0], y = pred_q[4 * b + 1];
            float z = pred_q[4 * b + 2], w = pred_q[4 * b + 3];
            float x2 = x * x, y2 = y * y, z2 = z * z;
            float xy = x * y, xz = x * z, yz = y * z;
            float wx = w * x, wy = w * y, wz = w * z;
            Rp[0] = 1.0f - 2.0f * (y2 + z2); Rp[1] = 2.0f * (xy - wz); Rp[2] = 2.0f * (xz + wy);
            Rp[3] = 2.0f * (xy + wz); Rp[4] = 1.0f - 2.0f * (x2 + z2); Rp[5] = 2.0f * (yz - wx);
            Rp[6] = 2.0f * (xz - wy); Rp[7] = 2.0f * (yz + wx); Rp[8] = 1.0f - 2.0f * (x2 + y2);
        }
        {
            float x = gt_q[4 * b + 0], y = gt_q[4 * b + 1];
            float z = gt_q[4 * b + 2], w = gt_q[4 * b + 3];
            float x2 = x * x, y2 = y * y, z2 = z * z;
            float xy = x * y, xz = x * z, yz = y * z;
            float wx = w * x, wy = w * y, wz = w * z;
            Rg[0] = 1.0f - 2.0f * (y2 + z2); Rg[1] = 2.0f * (xy - wz); Rg[2] = 2.0f * (xz + wy);
            Rg[3] = 2.0f * (xy + wz); Rg[4] = 1.0f - 2.0f * (x2 + z2); Rg[5] = 2.0f * (yz - wx);
            Rg[6] = 2.0f * (xz - wy); Rg[7] = 2.0f * (yz + wx); Rg[8] = 1.0f - 2.0f * (x2 + y2);
        }
        float d[9];
        #pragma unroll
        for (int i = 0; i < 9; i++) d[i] = Rp[i] - Rg[i];

        // M = dR^T dR (symmetric). Column k of dR is d[k], d[k+3], d[k+6].
        sc[0] = d[0]*d[0] + d[3]*d[3] + d[6]*d[6];
        sc[1] = d[1]*d[1] + d[4]*d[4] + d[7]*d[7];
        sc[2] = d[2]*d[2] + d[5]*d[5] + d[8]*d[8];
        sc[3] = 2.0f * (d[0]*d[1] + d[3]*d[4] + d[6]*d[7]);
        sc[4] = 2.0f * (d[0]*d[2] + d[3]*d[5] + d[6]*d[8]);
        sc[5] = 2.0f * (d[1]*d[2] + d[4]*d[5] + d[7]*d[8]);
    }
    __syncthreads();

    const float c0 = sc[0], c1 = sc[1], c2 = sc[2];
    const float c3 = sc[3], c4 = sc[4], c5 = sc[5];

    // Class index (dtype-robust + clamped: wrong guess -> rel_err, never a crash)
    int cidx;
    if (s_is64) cidx = (int)((const long long*)cls_raw)[b];
    else        cidx = ((const int*)cls_raw)[b];
    cidx = min(max(cidx, 0), CC - 1);

    const float4* __restrict__ base4 =
        (const float4*)(bank + (size_t)cidx * (size_t)(NN * 3));

    // Software-pipelined, fully unrolled: 4 iterations x 3 float4 (= 4 points each).
    // Independent accumulators break the serial FADD chain.
    float acc0 = 0.0f, acc1 = 0.0f, acc2 = 0.0f, acc3 = 0.0f;

    float4 a = base4[tid * 3 + 0];
    float4 v = base4[tid * 3 + 1];
    float4 w = base4[tid * 3 + 2];

    #pragma unroll
    for (int it = 0; it < (NN / 4) / NTHREADS; ++it) {
        float4 na, nv, nw;
        if (it < (NN / 4) / NTHREADS - 1) {
            int tri = (it + 1) * NTHREADS + tid;
            na = base4[tri * 3 + 0];
            nv = base4[tri * 3 + 1];
            nw = base4[tri * 3 + 2];
        }
        acc0 += point_norm(a.x, a.y, a.z, c0, c1, c2, c3, c4, c5);
        acc1 += point_norm(a.w, v.x, v.y, c0, c1, c2, c3, c4, c5);
        acc2 += point_norm(v.z, v.w, w.x, c0, c1, c2, c3, c4, c5);
        acc3 += point_norm(w.y, w.z, w.w, c0, c1, c2, c3, c4, c5);
        a = na; v = nv; w = nw;
    }

    float acc = (acc0 + acc1) + (acc2 + acc3);

    // ---- block reduce ----
    #pragma unroll
    for (int o = 16; o > 0; o >>= 1)
        acc += __shfl_xor_sync(0xffffffffu, acc, o);
    if ((tid & 31) == 0) swarp[tid >> 5] = acc;
    __syncthreads();
    if (tid == 0) {
        float s = 0.0f;
        #pragma unroll
        for (int i = 0; i < NTHREADS / 32; i++) s += swarp[i];
        g_partials[b] = s;
    }
}

// Single-warp, barrier-free final reduce: fixed order -> deterministic.
__global__ void __launch_bounds__(32)
reduce_kernel(float* __restrict__ out) {
    const int t = threadIdx.x;
    const float4* p4 = (const float4*)g_partials;  // 256 float4s

    double s = 0.0;
    #pragma unroll
    for (int i = 0; i < 8; i++) {               // 8 independent float4 loads/lane
        float4 v = p4[i * 32 + t];
        s += ((double)v.x + (double)v.y) + ((double)v.z + (double)v.w);
    }
    #pragma unroll
    for (int o = 16; o > 0; o >>= 1)
        s += __shfl_xor_sync(0xffffffffu, s, o);
    if (t == 0)
        out[0] = (float)(s / (double)((long long)BB * NN));
}

extern "C" void kernel_launch(void* const* d_in, const int* in_sizes, int n_in,
                              void* d_out, int out_size) {
    // Resolve inputs by element count (robust to metadata ordering):
    //   pred_q / gt_q : 4096 elems (order of appearance; loss is symmetric in swap)
    //   class_indices : 1024 elems
    //   point_bank    : 258048 elems
    const float* pred_q = nullptr;
    const float* gt_q   = nullptr;
    const void*  cls    = nullptr;
    const float* bank   = nullptr;

    for (int i = 0; i < n_in; i++) {
        int sz = in_sizes[i];
        if (sz == BB) {
            cls = d_in[i];
        } else if (sz == CC * NN * 3) {
            bank = (const float*)d_in[i];
        } else if (sz == BB * 4) {
            if (!pred_q) pred_q = (const float*)d_in[i];
            else         gt_q   = (const float*)d_in[i];
        }
    }
    float* out = (float*)d_out;

    point_loss_kernel<<<BB, NTHREADS>>>(pred_q, gt_q, cls, bank);
    reduce_kernel<<<1, 32>>>(out);
}